// round 4
// baseline (speedup 1.0000x reference)
#include <cuda_runtime.h>
#include <cuda_bf16.h>

static constexpr int BATCH = 2048;
static constexpr int NSLOT = 64;
static constexpr int FEAT  = 19;

__device__ float g_partials[BATCH];
__device__ int   g_count = 0;   // self-resetting -> graph-replay safe

// One CTA per batch, one thread per row (thread also owns column i for the
// acceptance step). Greedy mutual-best matching with proposal caching.
__global__ __launch_bounds__(NSLOT) void spotting_match_loss_kernel(
    const float* __restrict__ y_true,
    const float* __restrict__ y_pred,
    float*       __restrict__ out)
{
    const int b = blockIdx.x;
    const int i = threadIdx.x;

    __shared__ float              sp[NSLOT];      // p_j; taken columns -> 1e30
    __shared__ unsigned long long colkey[NSLOT];  // best proposal per column
    __shared__ int                srow2col[NSLOT];// final assignment row -> col
    __shared__ float              sred[NSLOT];
    __shared__ int                sflag;

    const float* yt = y_true + (size_t)b * NSLOT * FEAT;
    const float* yp = y_pred + (size_t)b * NSLOT * FEAT;

    const float a  = yt[i * FEAT + 0];   // alpha in {0,1}
    const float xi = yt[i * FEAT + 1];   // x_i

    sp[i]       = yp[i * FEAT + 1];      // p_i
    srow2col[i] = -1;
    colkey[i]   = 0ULL;
    __syncthreads();

    // Phase 0: alpha==1 rows; Phase 1: alpha==0 rows (taken columns persist).
    #pragma unroll 1
    for (int phase = 0; phase < 2; ++phase) {
        const bool in_phase = (phase == 0) ? (a > 0.5f) : (a <= 0.5f);

        int   bj = -1;      // cached proposal column
        float bv = 0.0f;    // cached proposal value

        for (;;) {
            const bool active = in_phase && (srow2col[i] < 0);
            if (__syncthreads_and(!active)) break;

            if (active) {
                // Rescan only when no cached proposal or it was taken.
                // Exactness: removing columns can never create a better
                // candidate, so a still-free cached best remains the argmax
                // (including the first-occurrence tie-break).
                if (bj < 0 || sp[bj] > 1e29f) {
                    bv = -3e38f; bj = 0;
                    #pragma unroll 8
                    for (int j = 0; j < NSLOT; ++j) {
                        const float d = 1.0f - fabsf(xi - sp[j]);
                        if (d > bv) { bv = d; bj = j; }   // strict > = jnp.argmax
                    }
                }
                // Propose: (value desc, row asc) packed monotonic key.
                // bv > 0 for a free column, so key != 0.
                atomicMax(&colkey[bj],
                    ((unsigned long long)__float_as_uint(bv) << 6) |
                    (unsigned long long)(63 - i));
            }
            __syncthreads();

            // Column accept (thread i = column i): any proposed column takes
            // its best proposer — exactly E = v*A*C (mutual best).
            const unsigned long long k = colkey[i];
            if (k) {
                const int r = 63 - (int)(k & 63ULL);
                srow2col[r] = i;
                sp[i]       = 1e30f;   // remove column
                colkey[i]   = 0ULL;
            }
            __syncthreads();
        }
    }

    // --- Loss contribution of row i against permuted prediction ---
    const int    pi  = srow2col[i];
    const float* ypp = yp + (size_t)pi * FEAT;

    float l;
    {
        const float yp0 = ypp[0];
        const float yp1 = ypp[1];
        const float d1  = xi - yp1;
        const float d0  = a - yp0;
        l = a * 5.0f * d1 * d1            // LAMBDA_COORD coord term
          + a * d0 * d0                   // obj confidence term
          + (1.0f - a) * 0.5f * d0 * d0;  // LAMBDA_NOOBJ term
        float s2 = 0.0f;
        #pragma unroll
        for (int f = 2; f < FEAT; ++f) {
            const float d = yt[i * FEAT + f] - ypp[f];
            s2 += d * d;
        }
        l += a * s2;
    }

    // Deterministic block tree-reduce
    sred[i] = l;
    __syncthreads();
    #pragma unroll
    for (int off = NSLOT / 2; off > 0; off >>= 1) {
        if (i < off) sred[i] += sred[i + off];
        __syncthreads();
    }

    // Publish partial; last CTA performs the fixed-order global reduction.
    if (i == 0) {
        g_partials[b] = sred[0];
        __threadfence();
        const int t = atomicAdd(&g_count, 1);
        sflag = (t == BATCH - 1);
    }
    __syncthreads();

    if (sflag) {
        float v = 0.0f;
        #pragma unroll
        for (int k = 0; k < BATCH / NSLOT; ++k) {
            v += g_partials[i + k * NSLOT];   // fixed order per thread
        }
        sred[i] = v;
        __syncthreads();
        #pragma unroll
        for (int off = NSLOT / 2; off > 0; off >>= 1) {
            if (i < off) sred[i] += sred[i + off];
            __syncthreads();
        }
        if (i == 0) {
            out[0]  = sred[0];
            g_count = 0;   // reset for next graph replay
        }
    }
}

extern "C" void kernel_launch(void* const* d_in, const int* in_sizes, int n_in,
                              void* d_out, int out_size)
{
    const float* y_true = (const float*)d_in[0];
    const float* y_pred = (const float*)d_in[1];
    float*       out    = (float*)d_out;

    spotting_match_loss_kernel<<<BATCH, NSLOT>>>(y_true, y_pred, out);
}

// round 5
// speedup vs baseline: 1.6843x; 1.6843x over previous
#include <cuda_runtime.h>
#include <cuda_bf16.h>

static constexpr int BATCH = 2048;
static constexpr int NSLOT = 64;
static constexpr int FEAT  = 19;
static constexpr int TPB   = 128;   // 2 threads per row

__device__ float g_partials[BATCH];
__device__ int   g_count = 0;       // self-resetting -> graph-replay safe

// One CTA per batch. Thread t: row i = t>>1, half h = t&1 (scans 32 columns).
// Greedy mutual-best matching identical to the reference scan semantics.
__global__ __launch_bounds__(TPB) void spotting_match_loss_kernel(
    const float* __restrict__ y_true,
    const float* __restrict__ y_pred,
    float*       __restrict__ out)
{
    const int b = blockIdx.x;
    const int t = threadIdx.x;
    const int i = t >> 1;            // row
    const int h = t & 1;             // half (0: cols 0..31, 1: cols 32..63)

    __shared__ float              sp[NSLOT];       // p_j; taken -> 1e30
    __shared__ unsigned long long colkey[NSLOT];   // best proposal per column
    __shared__ int                srow2col[NSLOT]; // row -> column
    __shared__ float              sred[TPB];
    __shared__ int                sflag;

    const float* yt = y_true + (size_t)b * NSLOT * FEAT;
    const float* yp = y_pred + (size_t)b * NSLOT * FEAT;

    const float a  = yt[i * FEAT + 0];
    const float xi = yt[i * FEAT + 1];

    if (t < NSLOT) {
        sp[t]       = yp[t * FEAT + 1];
        colkey[t]   = 0ULL;
        srow2col[t] = -1;
    }
    __syncthreads();

    // Phase 0: alpha==1 rows; Phase 1: alpha==0 rows (taken columns persist).
    #pragma unroll 1
    for (int phase = 0; phase < 2; ++phase) {
        const bool in_phase = (phase == 0) ? (a > 0.5f) : (a <= 0.5f);
        const int  jbase    = h * 32;

        for (;;) {
            const bool active = in_phase && (srow2col[i] < 0);
            if (__syncthreads_and(!active)) break;

            // Warp-uniform guard keeps the shfl converged while letting
            // fully-idle warps skip the scan.
            if (__any_sync(0xffffffffu, active)) {
                // 4 independent accumulators over CONTIGUOUS 8-col blocks:
                // ascending merge order + strict '>' preserves the
                // first-occurrence (lowest j) argmax tie-break exactly.
                float v0 = -3e38f, v1 = -3e38f, v2 = -3e38f, v3 = -3e38f;
                int   j0 = 0, j1 = 0, j2 = 0, j3 = 0;
                #pragma unroll
                for (int k = 0; k < 8; ++k) {
                    const float d0 = 1.0f - fabsf(xi - sp[jbase + k]);
                    const float d1 = 1.0f - fabsf(xi - sp[jbase + 8  + k]);
                    const float d2 = 1.0f - fabsf(xi - sp[jbase + 16 + k]);
                    const float d3 = 1.0f - fabsf(xi - sp[jbase + 24 + k]);
                    if (d0 > v0) { v0 = d0; j0 = jbase + k; }
                    if (d1 > v1) { v1 = d1; j1 = jbase + 8  + k; }
                    if (d2 > v2) { v2 = d2; j2 = jbase + 16 + k; }
                    if (d3 > v3) { v3 = d3; j3 = jbase + 24 + k; }
                }
                // Ascending merge (lower block wins ties -> lower j).
                if (v1 > v0) { v0 = v1; j0 = j1; }
                if (v2 > v0) { v0 = v2; j0 = j2; }
                if (v3 > v0) { v0 = v3; j0 = j3; }

                // Merge halves: partner is the adjacent lane (t^1 same warp).
                const float vO = __shfl_xor_sync(0xffffffffu, v0, 1);
                const int   jO = __shfl_xor_sync(0xffffffffu, j0, 1);
                if (h == 0) {
                    if (vO > v0) { v0 = vO; j0 = jO; }  // half1 has higher j
                    if (active) {
                        // key = (value desc, row asc); v0 > 0 so key != 0.
                        atomicMax(&colkey[j0],
                            ((unsigned long long)__float_as_uint(v0) << 6) |
                            (unsigned long long)(63 - i));
                    }
                }
            }
            __syncthreads();

            // Column accept (thread t = column t): proposed column takes its
            // best proposer — exactly E = v*A*C (mutual best).
            if (t < NSLOT) {
                const unsigned long long k = colkey[t];
                if (k) {
                    const int r = 63 - (int)(k & 63ULL);
                    srow2col[r] = t;
                    sp[t]       = 1e30f;
                    colkey[t]   = 0ULL;
                }
            }
            __syncthreads();
        }
    }

    // --- Loss: thread t<64 handles row t against permuted prediction ---
    float l = 0.0f;
    if (t < NSLOT) {
        const float  ar  = yt[t * FEAT + 0];
        const float  xr  = yt[t * FEAT + 1];
        const int    pi  = srow2col[t];
        const float* ypp = yp + (size_t)pi * FEAT;

        const float d1 = xr - ypp[1];
        const float d0 = ar - ypp[0];
        l = ar * 5.0f * d1 * d1
          + ar * d0 * d0
          + (1.0f - ar) * 0.5f * d0 * d0;
        float s2 = 0.0f;
        #pragma unroll
        for (int f = 2; f < FEAT; ++f) {
            const float d = yt[t * FEAT + f] - ypp[f];
            s2 += d * d;
        }
        l += ar * s2;
    }

    // Deterministic block tree-reduce
    sred[t] = l;
    __syncthreads();
    #pragma unroll
    for (int off = TPB / 2; off > 0; off >>= 1) {
        if (t < off) sred[t] += sred[t + off];
        __syncthreads();
    }

    // Publish partial; last CTA does the fixed-order global reduction.
    if (t == 0) {
        g_partials[b] = sred[0];
        __threadfence();
        const int c = atomicAdd(&g_count, 1);
        sflag = (c == BATCH - 1);
    }
    __syncthreads();

    if (sflag) {
        float v = 0.0f;
        #pragma unroll
        for (int k = 0; k < BATCH / TPB; ++k)
            v += g_partials[t + k * TPB];   // fixed order per thread
        sred[t] = v;
        __syncthreads();
        #pragma unroll
        for (int off = TPB / 2; off > 0; off >>= 1) {
            if (t < off) sred[t] += sred[t + off];
            __syncthreads();
        }
        if (t == 0) {
            out[0]  = sred[0];
            g_count = 0;    // reset for next graph replay
        }
    }
}

extern "C" void kernel_launch(void* const* d_in, const int* in_sizes, int n_in,
                              void* d_out, int out_size)
{
    const float* y_true = (const float*)d_in[0];
    const float* y_pred = (const float*)d_in[1];
    float*       out    = (float*)d_out;

    spotting_match_loss_kernel<<<BATCH, TPB>>>(y_true, y_pred, out);
}